// round 3
// baseline (speedup 1.0000x reference)
#include <cuda_runtime.h>
#include <cstdint>

// Problem constants (fixed by the reference)
#define M_TOK 256
#define K_DIM 1024
#define N_DIM 2048
#define E_NUM 64
#define TOPK  8
#define L_ROWS (M_TOK * TOPK)     // 2048 routed rows
#define CAP    32                 // rows per expert (balanced routing, exact)

// GEMM tiling
#define BM 32
#define BN 128
#define BK 32
#define STRIDE 36                 // smem row stride (words): conflict-free staging + frag LDS
#define THREADS 128               // 4 warps; each warp owns 32m x 32n
#define STAGES 3
#define NTILES (K_DIM / BK)       // 32

#define AS_WORDS (BM * STRIDE)              // 1152
#define BS_WORDS (BN * STRIDE)              // 4608
#define STAGE_WORDS (AS_WORDS + BS_WORDS)   // 5760 -> 23040 B/stage
#define SMEM_BYTES (STAGES * STAGE_WORDS * 4)  // 69120 B -> 3 blocks/SM

extern __shared__ float smem[];

__device__ __forceinline__ void cp16(float* dst_smem, const float* src) {
    uint32_t d = (uint32_t)__cvta_generic_to_shared(dst_smem);
    asm volatile("cp.async.cg.shared.global [%0], [%1], 16;" :: "r"(d), "l"(src));
}
__device__ __forceinline__ void cp_commit() {
    asm volatile("cp.async.commit_group;");
}
template <int N>
__device__ __forceinline__ void cp_wait() {
    asm volatile("cp.async.wait_group %0;" :: "n"(N));
}

__device__ __forceinline__ uint32_t f2tf(float x) {
    uint32_t r;
    asm("cvt.rna.tf32.f32 %0, %1;" : "=r"(r) : "f"(x));
    return r;
}

__device__ __forceinline__ void mma_tf32(float c[4], const uint32_t a[4], const uint32_t b[2]) {
    asm volatile(
        "mma.sync.aligned.m16n8k8.row.col.f32.tf32.tf32.f32 "
        "{%0,%1,%2,%3}, {%4,%5,%6,%7}, {%8,%9}, {%0,%1,%2,%3};"
        : "+f"(c[0]), "+f"(c[1]), "+f"(c[2]), "+f"(c[3])
        : "r"(a[0]), "r"(a[1]), "r"(a[2]), "r"(a[3]), "r"(b[0]), "r"(b[1]));
}

// ---------------------------------------------------------------------------
// One fused kernel. Block (nx, e):
//   1. scans topk_ids (8KB, L2-resident) to find the CAP=32 slots of expert e
//   2. grouped GEMM: gathered A rows (tf32-rounded post-LDS) @ B[e][n0:n0+128]^T
//      via a 3-stage cp.async pipeline, one __syncthreads per k-tile
//   3. epilogue fuses bias + routing weight + scatter to token order
// ---------------------------------------------------------------------------
__global__ __launch_bounds__(THREADS) void moe_fused_kernel(
    const float* __restrict__ A,      // [M, K]
    const float* __restrict__ B,      // [E, N, K]
    const float* __restrict__ bias,   // [E, N]
    const float* __restrict__ tw,     // [M, TOPK] flat
    const int*   __restrict__ ids,    // [M, TOPK] flat
    float* __restrict__ out)          // [L, N]
{
    __shared__ int   sSlot[CAP];
    __shared__ float sW[CAP];
    __shared__ int   sCnt;

    const int e    = blockIdx.y;
    const int n0   = blockIdx.x * BN;
    const int t    = threadIdx.x;
    const int warp = t >> 5;
    const int lane = t & 31;

    // --- routing: bucket this expert's 32 slots (order-invariant output) ---
    if (t == 0) sCnt = 0;
    __syncthreads();
#pragma unroll
    for (int l = t; l < L_ROWS; l += THREADS) {
        if (ids[l] == e) {
            int p = atomicAdd(&sCnt, 1);
            sSlot[p] = l;
        }
    }
    __syncthreads();
    if (t < CAP) sW[t] = tw[sSlot[t]];
    __syncthreads();

    // --- staging thread mapping ---
    const int ma  = lane;       // A: row within tile (t & 31)
    const int kfa = warp;       // A: float4 index (and +4)
    const int nb  = t >> 3;     // B: base n row (rows nb + j*16)
    const int kfb = t & 7;      // B: float4 index along k
    const float* arow = A + (size_t)(sSlot[ma] >> 3) * K_DIM + kfa * 4;  // token = l / TOPK
    const float* Bp   = B + ((size_t)e * N_DIM + n0 + nb) * K_DIM + kfb * 4;

    float acc[2][4][4];
#pragma unroll
    for (int i = 0; i < 2; i++)
#pragma unroll
        for (int j = 0; j < 4; j++)
#pragma unroll
            for (int k = 0; k < 4; k++) acc[i][j][k] = 0.f;

    // --- prologue: fill STAGES-1 pipeline stages ---
#pragma unroll
    for (int s = 0; s < STAGES - 1; s++) {
        float* As = smem + s * STAGE_WORDS;
        float* Bs = As + AS_WORDS;
        const int k0 = s * BK;
        cp16(As + ma * STRIDE + kfa * 4,       arow + k0);
        cp16(As + ma * STRIDE + (kfa + 4) * 4, arow + k0 + 16);
#pragma unroll
        for (int j = 0; j < 8; j++)
            cp16(Bs + (nb + j * 16) * STRIDE + kfb * 4, Bp + (size_t)j * 16 * K_DIM + k0);
        cp_commit();
    }

    // --- main loop: one sync per tile, loads always STAGES-1 tiles ahead ---
    for (int kt = 0; kt < NTILES; kt++) {
        cp_wait<STAGES - 2>();   // tile kt's group complete
        __syncthreads();

        // issue tile kt+STAGES-1 (dummy commit keeps group arithmetic exact)
        const int ktn = kt + STAGES - 1;
        if (ktn < NTILES) {
            const int stage = ktn % STAGES;
            float* As = smem + stage * STAGE_WORDS;
            float* Bs = As + AS_WORDS;
            const int k0 = ktn * BK;
            cp16(As + ma * STRIDE + kfa * 4,       arow + k0);
            cp16(As + ma * STRIDE + (kfa + 4) * 4, arow + k0 + 16);
#pragma unroll
            for (int j = 0; j < 8; j++)
                cp16(Bs + (nb + j * 16) * STRIDE + kfb * 4, Bp + (size_t)j * 16 * K_DIM + k0);
        }
        cp_commit();

        // compute current stage
        const float* As = smem + (kt % STAGES) * STAGE_WORDS;
        const float* Bs = As + AS_WORDS;
#pragma unroll
        for (int kk = 0; kk < 4; kk++) {
            const int ks = kk * 8 + (lane & 3);
            uint32_t a[2][4];
#pragma unroll
            for (int mf = 0; mf < 2; mf++) {
                int r = mf * 16 + (lane >> 2);
                a[mf][0] = f2tf(As[r * STRIDE + ks]);
                a[mf][1] = f2tf(As[(r + 8) * STRIDE + ks]);
                a[mf][2] = f2tf(As[r * STRIDE + ks + 4]);
                a[mf][3] = f2tf(As[(r + 8) * STRIDE + ks + 4]);
            }
#pragma unroll
            for (int nf = 0; nf < 4; nf++) {
                uint32_t b[2];
                int c = warp * 32 + nf * 8 + (lane >> 2);
                b[0] = f2tf(Bs[c * STRIDE + ks]);
                b[1] = f2tf(Bs[c * STRIDE + ks + 4]);
                mma_tf32(acc[0][nf], a[0], b);
                mma_tf32(acc[1][nf], a[1], b);
            }
        }
    }

    // --- epilogue: (acc + bias[e][n]) * w[l], scattered to out[l] ---
#pragma unroll
    for (int mf = 0; mf < 2; mf++) {
#pragma unroll
        for (int nf = 0; nf < 4; nf++) {
            int r   = mf * 16 + (lane >> 2);
            int col = n0 + warp * 32 + nf * 8 + (lane & 3) * 2;
            float2 bv = *(const float2*)(bias + (size_t)e * N_DIM + col);
            {
                int l = sSlot[r]; float wv = sW[r];
                float2 o = { (acc[mf][nf][0] + bv.x) * wv,
                             (acc[mf][nf][1] + bv.y) * wv };
                *(float2*)(out + (size_t)l * N_DIM + col) = o;
            }
            {
                int l = sSlot[r + 8]; float wv = sW[r + 8];
                float2 o = { (acc[mf][nf][2] + bv.x) * wv,
                             (acc[mf][nf][3] + bv.y) * wv };
                *(float2*)(out + (size_t)l * N_DIM + col) = o;
            }
        }
    }
}

extern "C" void kernel_launch(void* const* d_in, const int* in_sizes, int n_in,
                              void* d_out, int out_size) {
    (void)in_sizes; (void)n_in; (void)out_size;
    const float* A    = (const float*)d_in[0];   // [M, K] fp32
    const float* B    = (const float*)d_in[1];   // [E, N, K] fp32
    const float* bias = (const float*)d_in[2];   // [E, N] fp32
    const float* tw   = (const float*)d_in[3];   // [M, TOPK] fp32
    const int*   ids  = (const int*)d_in[4];     // [M, TOPK] int32
    float* out = (float*)d_out;                  // [M, TOPK, N] fp32

    static bool attr_set = false;
    if (!attr_set) {
        cudaFuncSetAttribute(moe_fused_kernel,
                             cudaFuncAttributeMaxDynamicSharedMemorySize, SMEM_BYTES);
        attr_set = true;
    }
    moe_fused_kernel<<<dim3(N_DIM / BN, E_NUM), THREADS, SMEM_BYTES>>>(
        A, B, bias, tw, ids, out);
}

// round 4
// speedup vs baseline: 1.2183x; 1.2183x over previous
#include <cuda_runtime.h>
#include <cstdint>

// Problem constants (fixed by the reference)
#define M_TOK 256
#define K_DIM 1024
#define N_DIM 2048
#define E_NUM 64
#define TOPK  8
#define L_ROWS (M_TOK * TOPK)     // 2048 routed rows
#define CAP    32                 // rows per expert (balanced routing, exact)

// GEMM tiling
#define BM 32
#define BN 128
#define BK 32
#define STRIDE 36                 // smem row stride (words): conflict-free staging + frag LDS
#define THREADS 256               // 8 warps; each warp owns 32m x 16n
#define STAGES 3
#define NTILES (K_DIM / BK)       // 32

#define AS_WORDS (BM * STRIDE)              // 1152
#define BS_WORDS (BN * STRIDE)              // 4608
#define STAGE_WORDS (AS_WORDS + BS_WORDS)   // 5760 -> 23040 B/stage
#define SMEM_BYTES (STAGES * STAGE_WORDS * 4)  // 69120 B -> 3 blocks/SM, 24 warps

extern __shared__ float smem[];

__device__ __forceinline__ void cp16(float* dst_smem, const float* src) {
    uint32_t d = (uint32_t)__cvta_generic_to_shared(dst_smem);
    asm volatile("cp.async.cg.shared.global [%0], [%1], 16;" :: "r"(d), "l"(src));
}
__device__ __forceinline__ void cp_commit() {
    asm volatile("cp.async.commit_group;");
}
template <int N>
__device__ __forceinline__ void cp_wait() {
    asm volatile("cp.async.wait_group %0;" :: "n"(N));
}

__device__ __forceinline__ uint32_t f2tf(float x) {
    uint32_t r;
    asm("cvt.rna.tf32.f32 %0, %1;" : "=r"(r) : "f"(x));
    return r;
}

__device__ __forceinline__ void mma_tf32(float c[4], const uint32_t a[4], const uint32_t b[2]) {
    asm volatile(
        "mma.sync.aligned.m16n8k8.row.col.f32.tf32.tf32.f32 "
        "{%0,%1,%2,%3}, {%4,%5,%6,%7}, {%8,%9}, {%0,%1,%2,%3};"
        : "+f"(c[0]), "+f"(c[1]), "+f"(c[2]), "+f"(c[3])
        : "r"(a[0]), "r"(a[1]), "r"(a[2]), "r"(a[3]), "r"(b[0]), "r"(b[1]));
}

// ---------------------------------------------------------------------------
// One fused kernel, 256 threads (8 warps). Block (nx, e):
//   1. scans topk_ids (8KB, L2-resident) to find the CAP=32 slots of expert e
//   2. grouped GEMM: gathered A rows (tf32-rounded post-LDS) @ B[e][n0:n0+128]^T
//      via a 3-stage cp.async pipeline, one __syncthreads per k-tile
//   3. epilogue fuses bias + routing weight + scatter to token order
// ---------------------------------------------------------------------------
__global__ __launch_bounds__(THREADS, 3) void moe_fused_kernel(
    const float* __restrict__ A,      // [M, K]
    const float* __restrict__ B,      // [E, N, K]
    const float* __restrict__ bias,   // [E, N]
    const float* __restrict__ tw,     // [M, TOPK] flat
    const int*   __restrict__ ids,    // [M, TOPK] flat
    float* __restrict__ out)          // [L, N]
{
    __shared__ int   sSlot[CAP];
    __shared__ float sW[CAP];
    __shared__ int   sCnt;

    const int e    = blockIdx.y;
    const int n0   = blockIdx.x * BN;
    const int t    = threadIdx.x;
    const int warp = t >> 5;
    const int lane = t & 31;

    // --- routing: bucket this expert's 32 slots (order-invariant output) ---
    if (t == 0) sCnt = 0;
    __syncthreads();
#pragma unroll
    for (int l = t; l < L_ROWS; l += THREADS) {
        if (ids[l] == e) {
            int p = atomicAdd(&sCnt, 1);
            sSlot[p] = l;
        }
    }
    __syncthreads();
    if (t < CAP) sW[t] = tw[sSlot[t]];
    __syncthreads();

    // --- staging thread mapping (256 threads) ---
    const int srow = t >> 3;     // 0..31: A row / B base row
    const int kf   = t & 7;      // float4 index along k
    const float* arow = A + (size_t)(sSlot[srow] >> 3) * K_DIM + kf * 4;  // token = l / TOPK
    const float* Bp   = B + ((size_t)e * N_DIM + n0 + srow) * K_DIM + kf * 4;

    float acc[2][2][4];
#pragma unroll
    for (int i = 0; i < 2; i++)
#pragma unroll
        for (int j = 0; j < 2; j++)
#pragma unroll
            for (int k = 0; k < 4; k++) acc[i][j][k] = 0.f;

    // --- prologue: fill STAGES-1 pipeline stages ---
#pragma unroll
    for (int s = 0; s < STAGES - 1; s++) {
        float* As = smem + s * STAGE_WORDS;
        float* Bs = As + AS_WORDS;
        const int k0 = s * BK;
        cp16(As + srow * STRIDE + kf * 4, arow + k0);
#pragma unroll
        for (int j = 0; j < 4; j++)
            cp16(Bs + (srow + j * 32) * STRIDE + kf * 4, Bp + (size_t)j * 32 * K_DIM + k0);
        cp_commit();
    }

    // --- main loop: one sync per tile, loads always STAGES-1 tiles ahead ---
    for (int kt = 0; kt < NTILES; kt++) {
        cp_wait<STAGES - 2>();   // tile kt's group complete
        __syncthreads();

        // issue tile kt+STAGES-1 (commit every iter keeps group count exact)
        const int ktn = kt + STAGES - 1;
        if (ktn < NTILES) {
            const int stage = ktn % STAGES;
            float* As = smem + stage * STAGE_WORDS;
            float* Bs = As + AS_WORDS;
            const int k0 = ktn * BK;
            cp16(As + srow * STRIDE + kf * 4, arow + k0);
#pragma unroll
            for (int j = 0; j < 4; j++)
                cp16(Bs + (srow + j * 32) * STRIDE + kf * 4, Bp + (size_t)j * 32 * K_DIM + k0);
        }
        cp_commit();

        // compute current stage; warp tile = rows 0..31, cols warp*16..warp*16+15
        const float* As = smem + (kt % STAGES) * STAGE_WORDS;
        const float* Bs = As + AS_WORDS;
#pragma unroll
        for (int kk = 0; kk < 4; kk++) {
            const int ks = kk * 8 + (lane & 3);
            uint32_t a[2][4];
#pragma unroll
            for (int mf = 0; mf < 2; mf++) {
                int r = mf * 16 + (lane >> 2);
                a[mf][0] = f2tf(As[r * STRIDE + ks]);
                a[mf][1] = f2tf(As[(r + 8) * STRIDE + ks]);
                a[mf][2] = f2tf(As[r * STRIDE + ks + 4]);
                a[mf][3] = f2tf(As[(r + 8) * STRIDE + ks + 4]);
            }
#pragma unroll
            for (int nf = 0; nf < 2; nf++) {
                uint32_t b[2];
                int c = warp * 16 + nf * 8 + (lane >> 2);
                b[0] = f2tf(Bs[c * STRIDE + ks]);
                b[1] = f2tf(Bs[c * STRIDE + ks + 4]);
                mma_tf32(acc[0][nf], a[0], b);
                mma_tf32(acc[1][nf], a[1], b);
            }
        }
    }

    // --- epilogue: (acc + bias[e][n]) * w[l], scattered to out[l] ---
#pragma unroll
    for (int mf = 0; mf < 2; mf++) {
#pragma unroll
        for (int nf = 0; nf < 2; nf++) {
            int r   = mf * 16 + (lane >> 2);
            int col = n0 + warp * 16 + nf * 8 + (lane & 3) * 2;
            float2 bv = *(const float2*)(bias + (size_t)e * N_DIM + col);
            {
                int l = sSlot[r]; float wv = sW[r];
                float2 o = { (acc[mf][nf][0] + bv.x) * wv,
                             (acc[mf][nf][1] + bv.y) * wv };
                *(float2*)(out + (size_t)l * N_DIM + col) = o;
            }
            {
                int l = sSlot[r + 8]; float wv = sW[r + 8];
                float2 o = { (acc[mf][nf][2] + bv.x) * wv,
                             (acc[mf][nf][3] + bv.y) * wv };
                *(float2*)(out + (size_t)l * N_DIM + col) = o;
            }
        }
    }
}

extern "C" void kernel_launch(void* const* d_in, const int* in_sizes, int n_in,
                              void* d_out, int out_size) {
    (void)in_sizes; (void)n_in; (void)out_size;
    const float* A    = (const float*)d_in[0];   // [M, K] fp32
    const float* B    = (const float*)d_in[1];   // [E, N, K] fp32
    const float* bias = (const float*)d_in[2];   // [E, N] fp32
    const float* tw   = (const float*)d_in[3];   // [M, TOPK] fp32
    const int*   ids  = (const int*)d_in[4];     // [M, TOPK] int32
    float* out = (float*)d_out;                  // [M, TOPK, N] fp32

    static bool attr_set = false;
    if (!attr_set) {
        cudaFuncSetAttribute(moe_fused_kernel,
                             cudaFuncAttributeMaxDynamicSharedMemorySize, SMEM_BYTES);
        attr_set = true;
    }
    moe_fused_kernel<<<dim3(N_DIM / BN, E_NUM), THREADS, SMEM_BYTES>>>(
        A, B, bias, tw, ids, out);
}